// round 15
// baseline (speedup 1.0000x reference)
#include <cuda_runtime.h>
#include <cuda_fp16.h>
#include <mma.h>
#include <math.h>
#include <stdint.h>

using namespace nvcuda;

#define H     768
#define IDIM  3072
#define NE    16
#define NS    2
#define NEXP  (NE + NS)
#define NTOK  2048
#define KSEL  2
#define NPAIR (NTOK * 4)
#define ROUTED_PAIRS (NTOK * KSEL)

#define BM  128
#define BN  64
#define LDB 72

#define BK_UP  96
#define LDK_UP 104
#define BK_DN  128
#define LDK_DN 136

#define CONVDN_BLOCKS 512

// ---------------- persistent scratch ----------------
__device__ __half d_wg_h[(size_t)NE * H * IDIM];
__device__ __half d_wu_h[(size_t)NE * H * IDIM];
__device__ __half d_wd_h[(size_t)NE * IDIM * H];
__device__ __half d_sg_h[(size_t)NS * H * IDIM];
__device__ __half d_su_h[(size_t)NS * H * IDIM];
__device__ __half d_sd_h[(size_t)NS * IDIM * H];
__device__ __half d_xg[(size_t)NPAIR * H];
__device__ __half d_act[(size_t)NPAIR * IDIM];
__device__ float d_y[(size_t)NPAIR * H];
__device__ int   d_pair_token[NPAIR];
__device__ float d_pair_weight[NPAIR];
__device__ int   d_token_pair[NTOK * 4];
__device__ int   d_cnt[NE];
__device__ int   d_fill[NE];
__device__ int   d_off[NEXP + 1];
__device__ int   d_tok_e[NTOK * KSEL];
__device__ float d_tok_w[NTOK * KSEL];

// ---------------- helpers ----------------
__device__ __forceinline__ uint2 cvtH4(float4 v) {
    uint32_t a = (uint32_t)__half_as_ushort(__float2half_rn(v.x))
               | ((uint32_t)__half_as_ushort(__float2half_rn(v.y)) << 16);
    uint32_t b = (uint32_t)__half_as_ushort(__float2half_rn(v.z))
               | ((uint32_t)__half_as_ushort(__float2half_rn(v.w)) << 16);
    return make_uint2(a, b);
}

__device__ __forceinline__ uint32_t smem_u32(const void* p) {
    uint32_t a;
    asm("{ .reg .u64 t; cvta.to.shared.u64 t, %1; cvt.u32.u64 %0, t; }" : "=r"(a) : "l"(p));
    return a;
}
__device__ __forceinline__ void cp16(uint32_t d, const void* s) {
    asm volatile("cp.async.cg.shared.global [%0], [%1], 16;" :: "r"(d), "l"(s) : "memory");
}
#define CP_COMMIT() asm volatile("cp.async.commit_group;" ::: "memory")
template<int N> __device__ __forceinline__ void cp_wait() {
    asm volatile("cp.async.wait_group %0;" :: "n"(N) : "memory");
}

// ---------------- routing ----------------
__global__ void init_kernel() {
    int t = threadIdx.x;
    if (t < NE) { d_cnt[t] = 0; d_fill[t] = 0; }
}

__global__ __launch_bounds__(256) void router_kernel(const float* __restrict__ x,
                                                     const float* __restrict__ gw) {
    int warp = (blockIdx.x * blockDim.x + threadIdx.x) >> 5;
    int lane = threadIdx.x & 31;
    if (warp >= NTOK) return;
    const float* xr = x + (size_t)warp * H;
    float acc[NE];
#pragma unroll
    for (int e = 0; e < NE; e++) acc[e] = 0.f;
    for (int h = lane; h < H; h += 32) {
        float xv = xr[h];
#pragma unroll
        for (int e = 0; e < NE; e++) acc[e] += xv * gw[e * H + h];
    }
#pragma unroll
    for (int e = 0; e < NE; e++) {
#pragma unroll
        for (int o = 16; o > 0; o >>= 1) acc[e] += __shfl_xor_sync(0xFFFFFFFFu, acc[e], o);
    }
    if (lane == 0) {
        float mx = acc[0];
#pragma unroll
        for (int e = 1; e < NE; e++) mx = fmaxf(mx, acc[e]);
        float p[NE]; float s = 0.f;
#pragma unroll
        for (int e = 0; e < NE; e++) { p[e] = expf(acc[e] - mx); s += p[e]; }
        float inv = 1.f / s;
#pragma unroll
        for (int e = 0; e < NE; e++) p[e] *= inv;
        int e0 = 0; float w0 = p[0];
        int e1 = -1; float w1 = -1.f;
#pragma unroll
        for (int e = 1; e < NE; e++) {
            if (p[e] > w0) { e1 = e0; w1 = w0; e0 = e; w0 = p[e]; }
            else if (p[e] > w1) { e1 = e; w1 = p[e]; }
        }
        float denom = w0 + w1 + 1e-8f;
        d_tok_e[warp * 2 + 0] = e0;  d_tok_w[warp * 2 + 0] = w0 / denom;
        d_tok_e[warp * 2 + 1] = e1;  d_tok_w[warp * 2 + 1] = w1 / denom;
        atomicAdd(&d_cnt[e0], 1);
        atomicAdd(&d_cnt[e1], 1);
    }
}

// build pairs with fused local scan
__global__ void build_pairs_kernel() {
    int t = blockIdx.x * blockDim.x + threadIdx.x;
    if (t >= NTOK) return;
    int offs[NE];
    {
        int acc = 0;
#pragma unroll
        for (int e = 0; e < NE; e++) { offs[e] = acc; acc += d_cnt[e]; }
    }
    if (t == 0) {
#pragma unroll
        for (int e = 0; e < NE; e++) d_off[e] = offs[e];
        d_off[NE]     = ROUTED_PAIRS;
        d_off[NE + 1] = ROUTED_PAIRS + NTOK;
        d_off[NE + 2] = ROUTED_PAIRS + 2 * NTOK;
    }
#pragma unroll
    for (int k = 0; k < KSEL; k++) {
        int e = d_tok_e[t * 2 + k];
        float w = d_tok_w[t * 2 + k];
        int pos = offs[e] + atomicAdd(&d_fill[e], 1);
        d_pair_token[pos] = t;
        d_pair_weight[pos] = w;
        d_token_pair[t * 4 + k] = pos;
    }
#pragma unroll
    for (int s = 0; s < NS; s++) {
        int pos = ROUTED_PAIRS + s * NTOK + t;
        d_pair_token[pos] = t;
        d_pair_weight[pos] = 0.5f;
        d_token_pair[t * 4 + 2 + s] = pos;
    }
}

// ---------------- fused gather + up-weight conversion ----------------
__global__ __launch_bounds__(192) void gather_convup_kernel(
    const float* __restrict__ x,
    const float4* __restrict__ wg,  const float4* __restrict__ wu,
    const float4* __restrict__ swg, const float4* __restrict__ swu) {
    if (blockIdx.x < NPAIR) {
        int p = blockIdx.x;
        int t = threadIdx.x;
        int tok = d_pair_token[p];
        float4 v = *(const float4*)(x + (size_t)tok * H + t * 4);
        *(uint2*)(d_xg + (size_t)p * H + t * 4) = cvtH4(v);
        return;
    }
    const int NR  = NE * H * IDIM / 4;
    const int NSH = NS * H * IDIM / 4;
    const int total = 2 * NR + 2 * NSH;
    int base = (blockIdx.x - NPAIR) * 192 + threadIdx.x;
    for (int i = base; i < total; i += 4096 * 192) {
        const float4* src; uint2* dst; int idx;
        if (i < NR)                { src = wg;  dst = (uint2*)d_wg_h; idx = i; }
        else if (i < 2 * NR)       { src = wu;  dst = (uint2*)d_wu_h; idx = i - NR; }
        else if (i < 2 * NR + NSH) { src = swg; dst = (uint2*)d_sg_h; idx = i - 2 * NR; }
        else                       { src = swu; dst = (uint2*)d_su_h; idx = i - 2 * NR - NSH; }
        dst[idx] = cvtH4(__ldg(src + idx));
    }
}

// ---------------- up/gate GEMM: BK=96 (8 stages), z==0 converts down-weights ----------------
#define ST_A_UP (BM * LDK_UP * 2)          // 26624
#define ST_B_UP (BK_UP * LDB * 2)          // 13824
#define ST_UP   (ST_A_UP + 2 * ST_B_UP)    // 54272
#define UP_SMEM (2 * ST_UP)                // 108544

__global__ __launch_bounds__(256) void up_kernel(const float4* __restrict__ wd,
                                                 const float4* __restrict__ swd) {
    int tid = threadIdx.x;

    if (blockIdx.z == 0) {
        int bid = blockIdx.y * gridDim.x + blockIdx.x;
        if (bid < CONVDN_BLOCKS) {
            const int NR  = NE * IDIM * H / 4;
            const int NSH = NS * IDIM * H / 4;
            const int total = NR + NSH;
            for (int i = bid * 256 + tid; i < total; i += CONVDN_BLOCKS * 256) {
                const float4* src; uint2* dst; int idx;
                if (i < NR) { src = wd;  dst = (uint2*)d_wd_h; idx = i; }
                else        { src = swd; dst = (uint2*)d_sd_h; idx = i - NR; }
                dst[idx] = cvtH4(__ldg(src + idx));
            }
        }
        return;
    }

    int ez  = blockIdx.z - 1;
    int off = d_off[ez];
    int cnt = d_off[ez + 1] - off;
    int m0  = blockIdx.y * BM;
    if (m0 >= cnt) return;
    int n0  = blockIdx.x * BN;

    const __half* Bg;
    const __half* Bu;
    if (ez < NE) {
        size_t wo = (size_t)ez * H * IDIM;
        Bg = d_wg_h + wo; Bu = d_wu_h + wo;
    } else {
        size_t wo = (size_t)(ez - NE) * H * IDIM;
        Bg = d_sg_h + wo; Bu = d_su_h + wo;
    }

    extern __shared__ char smraw[];
    uint32_t sb = smem_u32(smraw);
    float* ep = (float*)smraw;

    int wid = tid >> 5;
    int mbase = (wid & 3) * 32;
    int nbase = (wid >> 2) * 32;

    wmma::fragment<wmma::accumulator, 16, 16, 16, float> accg[2][2], accu[2][2];
#pragma unroll
    for (int i = 0; i < 2; i++)
#pragma unroll
        for (int j = 0; j < 2; j++) { wmma::fill_fragment(accg[i][j], 0.f); wmma::fill_fragment(accu[i][j], 0.f); }

    // stage chunks: A = 128 rows x 12 = 1536; B = 2 mats x 96 rows x 8 = 1536; total 3072
    auto load_stage = [&](int s, int k0) {
        uint32_t st = sb + s * ST_UP;
#pragma unroll
        for (int c = tid; c < 3072; c += 256) {
            if (c < 1536) {
                int row = c / 12, q = c - row * 12;
                int pr = off + min(m0 + row, cnt - 1);
                const __half* src = d_xg + (size_t)pr * H + k0 + q * 8;
                cp16(st + row * (LDK_UP * 2) + q * 16, src);
            } else {
                int b = c - 1536;
                int mat = (b >= 768) ? 1 : 0;
                int w = b - mat * 768;
                int r = w >> 3, q = w & 7;
                const __half* src = (mat ? Bu : Bg) + (size_t)(k0 + r) * IDIM + n0 + q * 8;
                cp16(st + ST_A_UP + mat * ST_B_UP + r * (LDB * 2) + q * 16, src);
            }
        }
    };

    const int KT = H / BK_UP;   // 8
    load_stage(0, 0);
    CP_COMMIT();

    for (int kt = 0; kt < KT; kt++) {
        if (kt + 1 < KT) { load_stage((kt + 1) & 1, (kt + 1) * BK_UP); CP_COMMIT(); cp_wait<1>(); }
        else cp_wait<0>();
        __syncthreads();

        char* st = smraw + (kt & 1) * ST_UP;
        __half* As  = (__half*)st;
        __half* BGs = (__half*)(st + ST_A_UP);
        __half* BUs = (__half*)(st + ST_A_UP + ST_B_UP);

#pragma unroll
        for (int ks = 0; ks < BK_UP / 16; ks++) {
            int kc = ks * 16;
            wmma::fragment<wmma::matrix_a, 16, 16, 16, __half, wmma::row_major> af[2];
#pragma unroll
            for (int i = 0; i < 2; i++)
                wmma::load_matrix_sync(af[i], &As[(mbase + i * 16) * LDK_UP + kc], LDK_UP);
#pragma unroll
            for (int j = 0; j < 2; j++) {
                wmma::fragment<wmma::matrix_b, 16, 16, 16, __half, wmma::row_major> bg, bu;
                wmma::load_matrix_sync(bg, &BGs[kc * LDB + nbase + j * 16], LDB);
                wmma::load_matrix_sync(bu, &BUs[kc * LDB + nbase + j * 16], LDB);
#pragma unroll
                for (int i = 0; i < 2; i++) {
                    wmma::mma_sync(accg[i][j], af[i], bg, accg[i][j]);
                    wmma::mma_sync(accu[i][j], af[i], bu, accu[i][j]);
                }
            }
        }
        __syncthreads();
    }

#pragma unroll
    for (int i = 0; i < 2; i++)
#pragma unroll
        for (int j = 0; j < 2; j++) {
#pragma unroll
            for (int e = 0; e < accg[i][j].num_elements; e++) {
                float g = accg[i][j].x[e];
                float u = accu[i][j].x[e];
                accg[i][j].x[e] = (g / (1.f + expf(-g))) * u;
            }
            wmma::store_matrix_sync(&ep[(mbase + i * 16) * BN + nbase + j * 16], accg[i][j], BN, wmma::mem_row_major);
        }
    __syncthreads();
#pragma unroll
    for (int idx = tid; idx < 2048; idx += 256) {
        int row = idx >> 4, c4 = idx & 15;
        if (m0 + row < cnt) {
            float4 v = *(float4*)&ep[row * BN + c4 * 4];
            *(uint2*)(d_act + (size_t)(off + m0 + row) * IDIM + n0 + c4 * 4) = cvtH4(v);
        }
    }
}

// ---------------- down GEMM: BK=128 (24 stages) ----------------
#define ST_A_DN (BM * LDK_DN * 2)          // 34816
#define ST_B_DN (BK_DN * LDB * 2)          // 18432
#define ST_DN   (ST_A_DN + ST_B_DN)        // 53248
#define DN_SMEM (2 * ST_DN)                // 106496

__global__ __launch_bounds__(256) void down_kernel() {
    int ez  = blockIdx.z;
    int off = d_off[ez];
    int cnt = d_off[ez + 1] - off;
    int m0  = blockIdx.y * BM;
    if (m0 >= cnt) return;
    int n0  = blockIdx.x * BN;

    const __half* Bw = (ez < NE) ? d_wd_h + (size_t)ez * IDIM * H
                                 : d_sd_h + (size_t)(ez - NE) * IDIM * H;

    extern __shared__ char smraw[];
    uint32_t sb = smem_u32(smraw);
    float* ep = (float*)smraw;

    int tid = threadIdx.x, wid = tid >> 5;
    int mbase = (wid & 3) * 32;
    int nbase = (wid >> 2) * 32;

    wmma::fragment<wmma::accumulator, 16, 16, 16, float> acc[2][2];
#pragma unroll
    for (int i = 0; i < 2; i++)
#pragma unroll
        for (int j = 0; j < 2; j++) wmma::fill_fragment(acc[i][j], 0.f);

    // stage chunks: A = 128 rows x 16 = 2048; B = 128 rows x 8 = 1024; total 3072
    auto load_stage = [&](int s, int k0) {
        uint32_t st = sb + s * ST_DN;
#pragma unroll
        for (int c = tid; c < 3072; c += 256) {
            if (c < 2048) {
                int row = c >> 4, q = c & 15;
                int pr = off + min(m0 + row, cnt - 1);
                const __half* src = d_act + (size_t)pr * IDIM + k0 + q * 8;
                cp16(st + row * (LDK_DN * 2) + q * 16, src);
            } else {
                int b = c - 2048;
                int r = b >> 3, q = b & 7;
                const __half* src = Bw + (size_t)(k0 + r) * H + n0 + q * 8;
                cp16(st + ST_A_DN + r * (LDB * 2) + q * 16, src);
            }
        }
    };

    const int KT = IDIM / BK_DN;   // 24
    load_stage(0, 0);
    CP_COMMIT();

    for (int kt = 0; kt < KT; kt++) {
        if (kt + 1 < KT) { load_stage((kt + 1) & 1, (kt + 1) * BK_DN); CP_COMMIT(); cp_wait<1>(); }
        else cp_wait<0>();
        __syncthreads();

        char* st = smraw + (kt & 1) * ST_DN;
        __half* As = (__half*)st;
        __half* Bs = (__half*)(st + ST_A_DN);

#pragma unroll
        for (int ks = 0; ks < BK_DN / 16; ks++) {
            int kc = ks * 16;
            wmma::fragment<wmma::matrix_a, 16, 16, 16, __half, wmma::row_major> af[2];
#pragma unroll
            for (int i = 0; i < 2; i++)
                wmma::load_matrix_sync(af[i], &As[(mbase + i * 16) * LDK_DN + kc], LDK_DN);
#pragma unroll
            for (int j = 0; j < 2; j++) {
                wmma::fragment<wmma::matrix_b, 16, 16, 16, __half, wmma::row_major> bf;
                wmma::load_matrix_sync(bf, &Bs[kc * LDB + nbase + j * 16], LDB);
#pragma unroll
                for (int i = 0; i < 2; i++)
                    wmma::mma_sync(acc[i][j], af[i], bf, acc[i][j]);
            }
        }
        __syncthreads();
    }

#pragma unroll
    for (int i = 0; i < 2; i++)
#pragma unroll
        for (int j = 0; j < 2; j++)
            wmma::store_matrix_sync(&ep[(mbase + i * 16) * BN + nbase + j * 16], acc[i][j], BN, wmma::mem_row_major);
    __syncthreads();
#pragma unroll
    for (int idx = tid; idx < 2048; idx += 256) {
        int row = idx >> 4, c4 = idx & 15;
        if (m0 + row < cnt)
            *(float4*)(d_y + (size_t)(off + m0 + row) * H + n0 + c4 * 4) = *(float4*)&ep[row * BN + c4 * 4];
    }
}

// ---------------- combine ----------------
__global__ __launch_bounds__(256) void combine_kernel(float* __restrict__ out) {
    int t = blockIdx.x;
    int p0 = d_token_pair[t * 4 + 0], p1 = d_token_pair[t * 4 + 1];
    int p2 = d_token_pair[t * 4 + 2], p3 = d_token_pair[t * 4 + 3];
    float w0 = d_pair_weight[p0], w1 = d_pair_weight[p1];
    float w2 = d_pair_weight[p2], w3 = d_pair_weight[p3];
    const float* y0 = d_y + (size_t)p0 * H;
    const float* y1 = d_y + (size_t)p1 * H;
    const float* y2 = d_y + (size_t)p2 * H;
    const float* y3 = d_y + (size_t)p3 * H;
    float* o = out + (size_t)t * H;
    for (int h = threadIdx.x; h < H; h += blockDim.x)
        o[h] = w0 * y0[h] + w1 * y1[h] + w2 * y2[h] + w3 * y3[h];
}

// ---------------- launch ----------------
extern "C" void kernel_launch(void* const* d_in, const int* in_sizes, int n_in,
                              void* d_out, int out_size) {
    const float* x      = (const float*)d_in[0];
    const float* gate_w = (const float*)d_in[1];
    const float* swg    = (const float*)d_in[2];
    const float* swu    = (const float*)d_in[3];
    const float* swd    = (const float*)d_in[4];
    const float* wg     = (const float*)d_in[5];
    const float* wu     = (const float*)d_in[6];
    const float* wd     = (const float*)d_in[7];
    float* out = (float*)d_out;

    cudaFuncSetAttribute(up_kernel,   cudaFuncAttributeMaxDynamicSharedMemorySize, UP_SMEM);
    cudaFuncSetAttribute(down_kernel, cudaFuncAttributeMaxDynamicSharedMemorySize, DN_SMEM);

    init_kernel<<<1, 32>>>();
    router_kernel<<<NTOK / 8, 256>>>(x, gate_w);
    build_pairs_kernel<<<NTOK / 256, 256>>>();

    gather_convup_kernel<<<NPAIR + 4096, 192>>>(x,
        (const float4*)wg, (const float4*)wu, (const float4*)swg, (const float4*)swu);

    dim3 gUp(IDIM / BN, NTOK / BM, NEXP + 1);   // (48, 16, 19)
    up_kernel<<<gUp, 256, UP_SMEM>>>((const float4*)wd, (const float4*)swd);

    dim3 gDown(H / BN, NTOK / BM, NEXP);        // (12, 16, 18)
    down_kernel<<<gDown, 256, DN_SMEM>>>();

    combine_kernel<<<NTOK, 256>>>(out);
}

// round 16
// speedup vs baseline: 1.0513x; 1.0513x over previous
#include <cuda_runtime.h>
#include <cuda_fp16.h>
#include <mma.h>
#include <math.h>
#include <stdint.h>

using namespace nvcuda;

#define H     768
#define IDIM  3072
#define NE    16
#define NS    2
#define NEXP  (NE + NS)
#define NTOK  2048
#define KSEL  2
#define NPAIR (NTOK * 4)
#define ROUTED_PAIRS (NTOK * KSEL)

#define BM  128
#define BN  64
#define BK  64
#define LDK 72
#define LDB 72

#define CONVDN_BLOCKS 512

// ---------------- persistent scratch ----------------
__device__ __half d_wg_h[(size_t)NE * H * IDIM];
__device__ __half d_wu_h[(size_t)NE * H * IDIM];
__device__ __half d_wd_h[(size_t)NE * IDIM * H];
__device__ __half d_sg_h[(size_t)NS * H * IDIM];
__device__ __half d_su_h[(size_t)NS * H * IDIM];
__device__ __half d_sd_h[(size_t)NS * IDIM * H];
__device__ __half d_xg[(size_t)NPAIR * H];
__device__ __half d_act[(size_t)NPAIR * IDIM];
__device__ float d_y[(size_t)NPAIR * H];
__device__ int   d_pair_token[NPAIR];
__device__ float d_pair_weight[NPAIR];
__device__ int   d_token_pair[NTOK * 4];
__device__ int   d_cnt[NE];    // zero-initialized at load; re-zeroed each run by gather_convup
__device__ int   d_fill[NE];
__device__ int   d_off[NEXP + 1];
__device__ int   d_tok_e[NTOK * KSEL];
__device__ float d_tok_w[NTOK * KSEL];

// ---------------- helpers ----------------
__device__ __forceinline__ uint2 cvtH4(float4 v) {
    uint32_t a = (uint32_t)__half_as_ushort(__float2half_rn(v.x))
               | ((uint32_t)__half_as_ushort(__float2half_rn(v.y)) << 16);
    uint32_t b = (uint32_t)__half_as_ushort(__float2half_rn(v.z))
               | ((uint32_t)__half_as_ushort(__float2half_rn(v.w)) << 16);
    return make_uint2(a, b);
}

__device__ __forceinline__ uint32_t smem_u32(const void* p) {
    uint32_t a;
    asm("{ .reg .u64 t; cvta.to.shared.u64 t, %1; cvt.u32.u64 %0, t; }" : "=r"(a) : "l"(p));
    return a;
}
__device__ __forceinline__ void cp16(uint32_t d, const void* s) {
    asm volatile("cp.async.cg.shared.global [%0], [%1], 16;" :: "r"(d), "l"(s) : "memory");
}
#define CP_COMMIT() asm volatile("cp.async.commit_group;" ::: "memory")
template<int N> __device__ __forceinline__ void cp_wait() {
    asm volatile("cp.async.wait_group %0;" :: "n"(N) : "memory");
}

// ---------------- routing ----------------
__global__ __launch_bounds__(256) void router_kernel(const float* __restrict__ x,
                                                     const float* __restrict__ gw) {
    int warp = (blockIdx.x * blockDim.x + threadIdx.x) >> 5;
    int lane = threadIdx.x & 31;
    if (warp >= NTOK) return;
    const float* xr = x + (size_t)warp * H;
    float acc[NE];
#pragma unroll
    for (int e = 0; e < NE; e++) acc[e] = 0.f;
    for (int h = lane; h < H; h += 32) {
        float xv = xr[h];
#pragma unroll
        for (int e = 0; e < NE; e++) acc[e] += xv * gw[e * H + h];
    }
#pragma unroll
    for (int e = 0; e < NE; e++) {
#pragma unroll
        for (int o = 16; o > 0; o >>= 1) acc[e] += __shfl_xor_sync(0xFFFFFFFFu, acc[e], o);
    }
    if (lane == 0) {
        float mx = acc[0];
#pragma unroll
        for (int e = 1; e < NE; e++) mx = fmaxf(mx, acc[e]);
        float p[NE]; float s = 0.f;
#pragma unroll
        for (int e = 0; e < NE; e++) { p[e] = expf(acc[e] - mx); s += p[e]; }
        float inv = 1.f / s;
#pragma unroll
        for (int e = 0; e < NE; e++) p[e] *= inv;
        int e0 = 0; float w0 = p[0];
        int e1 = -1; float w1 = -1.f;
#pragma unroll
        for (int e = 1; e < NE; e++) {
            if (p[e] > w0) { e1 = e0; w1 = w0; e0 = e; w0 = p[e]; }
            else if (p[e] > w1) { e1 = e; w1 = p[e]; }
        }
        float denom = w0 + w1 + 1e-8f;
        d_tok_e[warp * 2 + 0] = e0;  d_tok_w[warp * 2 + 0] = w0 / denom;
        d_tok_e[warp * 2 + 1] = e1;  d_tok_w[warp * 2 + 1] = w1 / denom;
        atomicAdd(&d_cnt[e0], 1);
        atomicAdd(&d_cnt[e1], 1);
    }
}

// build pairs with fused local scan
__global__ void build_pairs_kernel() {
    int t = blockIdx.x * blockDim.x + threadIdx.x;
    if (t >= NTOK) return;
    int offs[NE];
    {
        int acc = 0;
#pragma unroll
        for (int e = 0; e < NE; e++) { offs[e] = acc; acc += d_cnt[e]; }
    }
    if (t == 0) {
#pragma unroll
        for (int e = 0; e < NE; e++) d_off[e] = offs[e];
        d_off[NE]     = ROUTED_PAIRS;
        d_off[NE + 1] = ROUTED_PAIRS + NTOK;
        d_off[NE + 2] = ROUTED_PAIRS + 2 * NTOK;
    }
#pragma unroll
    for (int k = 0; k < KSEL; k++) {
        int e = d_tok_e[t * 2 + k];
        float w = d_tok_w[t * 2 + k];
        int pos = offs[e] + atomicAdd(&d_fill[e], 1);
        d_pair_token[pos] = t;
        d_pair_weight[pos] = w;
        d_token_pair[t * 4 + k] = pos;
    }
#pragma unroll
    for (int s = 0; s < NS; s++) {
        int pos = ROUTED_PAIRS + s * NTOK + t;
        d_pair_token[pos] = t;
        d_pair_weight[pos] = 0.5f;
        d_token_pair[t * 4 + 2 + s] = pos;
    }
}

// ---------------- fused gather + up-weight conversion (+ counter reset) ----------------
__global__ __launch_bounds__(192) void gather_convup_kernel(
    const float* __restrict__ x,
    const float4* __restrict__ wg,  const float4* __restrict__ wu,
    const float4* __restrict__ swg, const float4* __restrict__ swu) {
    if (blockIdx.x < NPAIR) {
        int p = blockIdx.x;
        int t = threadIdx.x;
        int tok = d_pair_token[p];
        float4 v = *(const float4*)(x + (size_t)tok * H + t * 4);
        *(uint2*)(d_xg + (size_t)p * H + t * 4) = cvtH4(v);
        return;
    }
    // reset routing counters for the next invocation (build_pairs has completed)
    if (blockIdx.x == NPAIR && threadIdx.x < NE) {
        d_cnt[threadIdx.x] = 0;
        d_fill[threadIdx.x] = 0;
    }
    const int NR  = NE * H * IDIM / 4;
    const int NSH = NS * H * IDIM / 4;
    const int total = 2 * NR + 2 * NSH;
    int base = (blockIdx.x - NPAIR) * 192 + threadIdx.x;
    for (int i = base; i < total; i += 4096 * 192) {
        const float4* src; uint2* dst; int idx;
        if (i < NR)                { src = wg;  dst = (uint2*)d_wg_h; idx = i; }
        else if (i < 2 * NR)       { src = wu;  dst = (uint2*)d_wu_h; idx = i - NR; }
        else if (i < 2 * NR + NSH) { src = swg; dst = (uint2*)d_sg_h; idx = i - 2 * NR; }
        else                       { src = swu; dst = (uint2*)d_su_h; idx = i - 2 * NR - NSH; }
        dst[idx] = cvtH4(__ldg(src + idx));
    }
}

// ---------------- up/gate GEMM (z==0 slice converts down-weights) ----------------
#define ST_A   (BM * LDK * 2)            // 18432
#define ST_B1  (BK * LDB * 2)            // 9216
#define ST_UP  (ST_A + 2 * ST_B1)        // 36864
#define UP_SMEM (2 * ST_UP)              // 73728

__global__ __launch_bounds__(256) void up_kernel(const float4* __restrict__ wd,
                                                 const float4* __restrict__ swd) {
    int tid = threadIdx.x;

    if (blockIdx.z == 0) {
        int bid = blockIdx.y * gridDim.x + blockIdx.x;
        if (bid < CONVDN_BLOCKS) {
            const int NR  = NE * IDIM * H / 4;
            const int NSH = NS * IDIM * H / 4;
            const int total = NR + NSH;
            for (int i = bid * 256 + tid; i < total; i += CONVDN_BLOCKS * 256) {
                const float4* src; uint2* dst; int idx;
                if (i < NR) { src = wd;  dst = (uint2*)d_wd_h; idx = i; }
                else        { src = swd; dst = (uint2*)d_sd_h; idx = i - NR; }
                dst[idx] = cvtH4(__ldg(src + idx));
            }
        }
        return;
    }

    int ez  = blockIdx.z - 1;
    int off = d_off[ez];
    int cnt = d_off[ez + 1] - off;
    int m0  = blockIdx.y * BM;
    if (m0 >= cnt) return;
    int n0  = blockIdx.x * BN;

    const __half* Bg;
    const __half* Bu;
    if (ez < NE) {
        size_t wo = (size_t)ez * H * IDIM;
        Bg = d_wg_h + wo; Bu = d_wu_h + wo;
    } else {
        size_t wo = (size_t)(ez - NE) * H * IDIM;
        Bg = d_sg_h + wo; Bu = d_su_h + wo;
    }

    extern __shared__ char smraw[];
    uint32_t sb = smem_u32(smraw);
    float* ep = (float*)smraw;

    int wid = tid >> 5;
    int mbase = (wid & 3) * 32;
    int nbase = (wid >> 2) * 32;

    wmma::fragment<wmma::accumulator, 16, 16, 16, float> accg[2][2], accu[2][2];
#pragma unroll
    for (int i = 0; i < 2; i++)
#pragma unroll
        for (int j = 0; j < 2; j++) { wmma::fill_fragment(accg[i][j], 0.f); wmma::fill_fragment(accu[i][j], 0.f); }

    auto load_stage = [&](int s, int k0) {
        uint32_t st = sb + s * ST_UP;
#pragma unroll
        for (int c = tid; c < 2048; c += 256) {
            if (c < 1024) {
                int row = c >> 3, q = c & 7;
                int pr = off + min(m0 + row, cnt - 1);
                const __half* src = d_xg + (size_t)pr * H + k0 + q * 8;
                cp16(st + row * (LDK * 2) + q * 16, src);
            } else {
                int b = c - 1024;
                int mat = b >> 9, r = (b >> 3) & 63, q = b & 7;
                const __half* src = (mat ? Bu : Bg) + (size_t)(k0 + r) * IDIM + n0 + q * 8;
                cp16(st + ST_A + mat * ST_B1 + r * (LDB * 2) + q * 16, src);
            }
        }
    };

    const int KT = H / BK;   // 12
    load_stage(0, 0);
    CP_COMMIT();

    for (int kt = 0; kt < KT; kt++) {
        if (kt + 1 < KT) { load_stage((kt + 1) & 1, (kt + 1) * BK); CP_COMMIT(); cp_wait<1>(); }
        else cp_wait<0>();
        __syncthreads();

        char* st = smraw + (kt & 1) * ST_UP;
        __half* As  = (__half*)st;
        __half* BGs = (__half*)(st + ST_A);
        __half* BUs = (__half*)(st + ST_A + ST_B1);

#pragma unroll
        for (int ks = 0; ks < BK / 16; ks++) {
            int kc = ks * 16;
            wmma::fragment<wmma::matrix_a, 16, 16, 16, __half, wmma::row_major> af[2];
#pragma unroll
            for (int i = 0; i < 2; i++)
                wmma::load_matrix_sync(af[i], &As[(mbase + i * 16) * LDK + kc], LDK);
#pragma unroll
            for (int j = 0; j < 2; j++) {
                wmma::fragment<wmma::matrix_b, 16, 16, 16, __half, wmma::row_major> bg, bu;
                wmma::load_matrix_sync(bg, &BGs[kc * LDB + nbase + j * 16], LDB);
                wmma::load_matrix_sync(bu, &BUs[kc * LDB + nbase + j * 16], LDB);
#pragma unroll
                for (int i = 0; i < 2; i++) {
                    wmma::mma_sync(accg[i][j], af[i], bg, accg[i][j]);
                    wmma::mma_sync(accu[i][j], af[i], bu, accu[i][j]);
                }
            }
        }
        __syncthreads();
    }

#pragma unroll
    for (int i = 0; i < 2; i++)
#pragma unroll
        for (int j = 0; j < 2; j++) {
#pragma unroll
            for (int e = 0; e < accg[i][j].num_elements; e++) {
                float g = accg[i][j].x[e];
                float u = accu[i][j].x[e];
                accg[i][j].x[e] = (g / (1.f + expf(-g))) * u;
            }
            wmma::store_matrix_sync(&ep[(mbase + i * 16) * BN + nbase + j * 16], accg[i][j], BN, wmma::mem_row_major);
        }
    __syncthreads();
#pragma unroll
    for (int idx = tid; idx < 2048; idx += 256) {
        int row = idx >> 4, c4 = idx & 15;
        if (m0 + row < cnt) {
            float4 v = *(float4*)&ep[row * BN + c4 * 4];
            *(uint2*)(d_act + (size_t)(off + m0 + row) * IDIM + n0 + c4 * 4) = cvtH4(v);
        }
    }
}

// ---------------- down GEMM ----------------
#define ST_DN (ST_A + ST_B1)            // 27648
#define EP_BYTES (BM * BN * 4)          // 32768
#define DN_SMEM ((2 * ST_DN) > EP_BYTES ? (2 * ST_DN) : EP_BYTES)   // 55296

__global__ __launch_bounds__(256) void down_kernel() {
    int ez  = blockIdx.z;
    int off = d_off[ez];
    int cnt = d_off[ez + 1] - off;
    int m0  = blockIdx.y * BM;
    if (m0 >= cnt) return;
    int n0  = blockIdx.x * BN;

    const __half* Bw = (ez < NE) ? d_wd_h + (size_t)ez * IDIM * H
                                 : d_sd_h + (size_t)(ez - NE) * IDIM * H;

    extern __shared__ char smraw[];
    uint32_t sb = smem_u32(smraw);
    float* ep = (float*)smraw;

    int tid = threadIdx.x, wid = tid >> 5;
    int mbase = (wid & 3) * 32;
    int nbase = (wid >> 2) * 32;

    wmma::fragment<wmma::accumulator, 16, 16, 16, float> acc[2][2];
#pragma unroll
    for (int i = 0; i < 2; i++)
#pragma unroll
        for (int j = 0; j < 2; j++) wmma::fill_fragment(acc[i][j], 0.f);

    auto load_stage = [&](int s, int k0) {
        uint32_t st = sb + s * ST_DN;
#pragma unroll
        for (int c = tid; c < 1536; c += 256) {
            if (c < 1024) {
                int row = c >> 3, q = c & 7;
                int pr = off + min(m0 + row, cnt - 1);
                const __half* src = d_act + (size_t)pr * IDIM + k0 + q * 8;
                cp16(st + row * (LDK * 2) + q * 16, src);
            } else {
                int b = c - 1024;
                int r = b >> 3, q = b & 7;
                const __half* src = Bw + (size_t)(k0 + r) * H + n0 + q * 8;
                cp16(st + ST_A + r * (LDB * 2) + q * 16, src);
            }
        }
    };

    const int KT = IDIM / BK;   // 48
    load_stage(0, 0);
    CP_COMMIT();

    for (int kt = 0; kt < KT; kt++) {
        if (kt + 1 < KT) { load_stage((kt + 1) & 1, (kt + 1) * BK); CP_COMMIT(); cp_wait<1>(); }
        else cp_wait<0>();
        __syncthreads();

        char* st = smraw + (kt & 1) * ST_DN;
        __half* As = (__half*)st;
        __half* Bs = (__half*)(st + ST_A);

#pragma unroll
        for (int ks = 0; ks < BK / 16; ks++) {
            int kc = ks * 16;
            wmma::fragment<wmma::matrix_a, 16, 16, 16, __half, wmma::row_major> af[2];
#pragma unroll
            for (int i = 0; i < 2; i++)
                wmma::load_matrix_sync(af[i], &As[(mbase + i * 16) * LDK + kc], LDK);
#pragma unroll
            for (int j = 0; j < 2; j++) {
                wmma::fragment<wmma::matrix_b, 16, 16, 16, __half, wmma::row_major> bf;
                wmma::load_matrix_sync(bf, &Bs[kc * LDB + nbase + j * 16], LDB);
#pragma unroll
                for (int i = 0; i < 2; i++)
                    wmma::mma_sync(acc[i][j], af[i], bf, acc[i][j]);
            }
        }
        __syncthreads();
    }

#pragma unroll
    for (int i = 0; i < 2; i++)
#pragma unroll
        for (int j = 0; j < 2; j++)
            wmma::store_matrix_sync(&ep[(mbase + i * 16) * BN + nbase + j * 16], acc[i][j], BN, wmma::mem_row_major);
    __syncthreads();
#pragma unroll
    for (int idx = tid; idx < 2048; idx += 256) {
        int row = idx >> 4, c4 = idx & 15;
        if (m0 + row < cnt)
            *(float4*)(d_y + (size_t)(off + m0 + row) * H + n0 + c4 * 4) = *(float4*)&ep[row * BN + c4 * 4];
    }
}

// ---------------- combine (vectorized: 192 threads x float4 = 768) ----------------
__global__ __launch_bounds__(192) void combine_kernel(float* __restrict__ out) {
    int t = blockIdx.x;
    int p0 = d_token_pair[t * 4 + 0], p1 = d_token_pair[t * 4 + 1];
    int p2 = d_token_pair[t * 4 + 2], p3 = d_token_pair[t * 4 + 3];
    float w0 = d_pair_weight[p0], w1 = d_pair_weight[p1];
    float w2 = d_pair_weight[p2], w3 = d_pair_weight[p3];
    int h = threadIdx.x * 4;
    float4 a = *(const float4*)(d_y + (size_t)p0 * H + h);
    float4 b = *(const float4*)(d_y + (size_t)p1 * H + h);
    float4 c = *(const float4*)(d_y + (size_t)p2 * H + h);
    float4 d = *(const float4*)(d_y + (size_t)p3 * H + h);
    float4 o;
    o.x = w0 * a.x + w1 * b.x + w2 * c.x + w3 * d.x;
    o.y = w0 * a.y + w1 * b.y + w2 * c.y + w3 * d.y;
    o.z = w0 * a.z + w1 * b.z + w2 * c.z + w3 * d.z;
    o.w = w0 * a.w + w1 * b.w + w2 * c.w + w3 * d.w;
    *(float4*)(out + (size_t)t * H + h) = o;
}

// ---------------- launch ----------------
extern "C" void kernel_launch(void* const* d_in, const int* in_sizes, int n_in,
                              void* d_out, int out_size) {
    const float* x      = (const float*)d_in[0];
    const float* gate_w = (const float*)d_in[1];
    const float* swg    = (const float*)d_in[2];
    const float* swu    = (const float*)d_in[3];
    const float* swd    = (const float*)d_in[4];
    const float* wg     = (const float*)d_in[5];
    const float* wu     = (const float*)d_in[6];
    const float* wd     = (const float*)d_in[7];
    float* out = (float*)d_out;

    cudaFuncSetAttribute(up_kernel,   cudaFuncAttributeMaxDynamicSharedMemorySize, UP_SMEM);
    cudaFuncSetAttribute(down_kernel, cudaFuncAttributeMaxDynamicSharedMemorySize, DN_SMEM);

    router_kernel<<<NTOK / 8, 256>>>(x, gate_w);
    build_pairs_kernel<<<NTOK / 256, 256>>>();

    gather_convup_kernel<<<NPAIR + 4096, 192>>>(x,
        (const float4*)wg, (const float4*)wu, (const float4*)swg, (const float4*)swu);

    dim3 gUp(IDIM / BN, NTOK / BM, NEXP + 1);   // (48, 16, 19)
    up_kernel<<<gUp, 256, UP_SMEM>>>((const float4*)wd, (const float4*)swd);

    dim3 gDown(H / BN, NTOK / BM, NEXP);        // (12, 16, 18)
    down_kernel<<<gDown, 256, DN_SMEM>>>();

    combine_kernel<<<NTOK, 192>>>(out);
}